// round 15
// baseline (speedup 1.0000x reference)
#include <cuda_runtime.h>
#include <cuda_fp16.h>
#include <cstdint>

#define B_  4
#define S_  2048
#define H_  16
#define HD_ 64
#define D_  1024
#define M_TOT (B_*S_)   // 8192

__device__ __half g_qkv[(size_t)3*B_*H_*S_*HD_]; // seg0 Q [b][h][s][hd], seg1 K same, seg2 V [b][h][hd][s]
__device__ __half g_attn[(size_t)M_TOT*D_];      // [b*s][d]
__device__ __half g_xr[(size_t)M_TOT*D_];
__device__ __half g_w1[(size_t)3*D_*D_];
__device__ __half g_w2[(size_t)D_*D_];

__device__ __forceinline__ uint32_t smem_u32(const void* p) {
    uint32_t a;
    asm("{ .reg .u64 t; cvta.to.shared.u64 t, %1; cvt.u32.u64 %0, t; }" : "=r"(a) : "l"(p));
    return a;
}
__device__ __forceinline__ void cp16(uint32_t s, const void* g) {
    asm volatile("cp.async.cg.shared.global [%0], [%1], 16;"
                 :: "r"(s), "l"(__cvta_generic_to_global(g)) : "memory");
}
__device__ __forceinline__ void cp_commit() {
    asm volatile("cp.async.commit_group;" ::: "memory");
}
__device__ __forceinline__ void cp_wait0() {
    asm volatile("cp.async.wait_group 0;" ::: "memory");
}
__device__ __forceinline__ void cp_wait1() {
    asm volatile("cp.async.wait_group 1;" ::: "memory");
}
__device__ __forceinline__ void ldmx4(uint32_t* r, uint32_t addr) {
    asm volatile("ldmatrix.sync.aligned.m8n8.x4.shared.b16 {%0,%1,%2,%3}, [%4];"
                 : "=r"(r[0]), "=r"(r[1]), "=r"(r[2]), "=r"(r[3]) : "r"(addr));
}
__device__ __forceinline__ void bar_named(int id, int cnt) {
    asm volatile("bar.sync %0, %1;" :: "r"(id), "r"(cnt) : "memory");
}
__device__ __forceinline__ uint32_t ex2_h2(uint32_t y) {
    uint32_t p;
    asm("ex2.approx.f16x2 %0, %1;" : "=r"(p) : "r"(y));
    return p;
}
__device__ __forceinline__ uint32_t pack_h2(float a, float b) {
    uint32_t r;
    asm("cvt.rn.f16x2.f32 %0, %2, %1;" : "=r"(r) : "f"(a), "f"(b));
    return r;
}

// mma.sync m16n8k16 fp16 in / fp32 accum
__device__ __forceinline__ void mma_f16(float* d, const uint32_t* a, const uint32_t* b) {
    asm volatile(
        "mma.sync.aligned.m16n8k16.row.col.f32.f16.f16.f32 "
        "{%0,%1,%2,%3}, {%4,%5,%6,%7}, {%8,%9}, {%0,%1,%2,%3};"
        : "+f"(d[0]), "+f"(d[1]), "+f"(d[2]), "+f"(d[3])
        : "r"(a[0]), "r"(a[1]), "r"(a[2]), "r"(a[3]), "r"(b[0]), "r"(b[1]));
}

// ---------------------------------------------------------------------------
// Fused fp32 -> fp16 conversion for x, w_in, w_out (one launch).
// ---------------------------------------------------------------------------
#define N4_X  (M_TOT*D_/4)
#define N4_W1 (3*D_*D_/4)
#define N4_W2 (D_*D_/4)
#define N4_ALL (N4_X + N4_W1 + N4_W2)

__global__ void f2h_all_kernel(const float4* __restrict__ x,
                               const float4* __restrict__ w1,
                               const float4* __restrict__ w2)
{
    __half2* dx  = (__half2*)g_xr;
    __half2* dw1 = (__half2*)g_w1;
    __half2* dw2 = (__half2*)g_w2;
    int i = blockIdx.x * blockDim.x + threadIdx.x;
    if (i >= N4_ALL) return;
    const float4* src; __half2* dst; int j;
    if (i < N4_X)              { src = x;  dst = dx;  j = i; }
    else if (i < N4_X + N4_W1) { src = w1; dst = dw1; j = i - N4_X; }
    else                       { src = w2; dst = dw2; j = i - N4_X - N4_W1; }
    float4 v = src[j];
    dst[2*j]   = __floats2half2_rn(v.x, v.y);
    dst[2*j+1] = __floats2half2_rn(v.z, v.w);
}

// ---------------------------------------------------------------------------
// fp16 tensor GEMM, cp.async 3-stage pipeline, BK=64 halfs, ldmatrix frags.
// 128x128 CTA tile, 8 warps (2m x 4n), warp tile 64x32 (4x4 m16n8k16).
// MODE 0: nhalf selects head-half n-tiles {nhalf*4 + seg*8 + 0..3 : seg<3}.
// ---------------------------------------------------------------------------
#define GBK    64
#define SROW   72
#define STGH   (256*SROW)
#define GE_SMEM (3*STGH*2)            // 110592 B

template<int MODE>
__global__ __launch_bounds__(256, 2) void tc_gemm(
    const float* __restrict__ bias, float* __restrict__ out, int N, int K, int nhalf)
{
    extern __shared__ __align__(16) __half smh[];
    uint32_t* smw = (uint32_t*)smh;
    const __half* A = MODE ? g_attn : g_xr;
    const __half* W = MODE ? g_w2   : g_w1;

    int tid  = threadIdx.x;
    int wid  = tid >> 5;
    int lane = tid & 31;
    int gr = lane >> 2, tg = lane & 3;
    int mw = (wid >> 2) * 64;
    int nw = (wid & 3) * 32;
    int m0 = blockIdx.y * 128;
    int n0;
    if (MODE == 0) {
        int nt = nhalf * 4 + (blockIdx.x >> 2) * 8 + (blockIdx.x & 3);
        n0 = nt * 128;
    } else {
        n0 = blockIdx.x * 128;
    }
    uint32_t sb = smem_u32(smh);

    int lA = (mw + (lane & 15)) * SROW + (lane >> 4) * 8;
    int lB = (128 + nw + ((lane >> 4) << 3) + (lane & 7)) * SROW
           + ((lane >> 3) & 1) * 8;

    float acc[4][4][4] = {};

    auto issue = [&](int c, int st) {
        int koff = c * GBK;
        uint32_t base = sb + (uint32_t)st * STGH * 2;
#pragma unroll
        for (int it = 0; it < 8; it++) {
            int lin = it * 256 + tid;
            int isB = lin >> 10;
            int row = (lin >> 3) & 127;
            int c8  = (lin & 7) * 8;
            const __half* src = (isB ? W + (size_t)(n0 + row) * K
                                     : A + (size_t)(m0 + row) * K) + koff + c8;
            cp16(base + (uint32_t)isB * (128*SROW*2) + (uint32_t)(row * SROW + c8) * 2, src);
        }
        cp_commit();
    };

    const int NC = K / GBK;
    issue(0, 0);
    if (NC > 1) issue(1, 1);

    for (int c = 0; c < NC; c++) {
        int st = c % 3;
        if (c + 1 < NC) cp_wait1(); else cp_wait0();
        __syncthreads();
        if (c + 2 < NC) issue(c + 2, (c + 2) % 3);

        uint32_t stb = sb + (uint32_t)st * STGH * 2;
#pragma unroll
        for (int k16 = 0; k16 < 4; k16++) {
            int kk = k16 * 16;
            uint32_t af[4][4], bf[4][2];
#pragma unroll
            for (int mi = 0; mi < 4; mi++)
                ldmx4(af[mi], stb + (uint32_t)(lA + mi * 16 * SROW + kk) * 2);
#pragma unroll
            for (int np = 0; np < 2; np++) {
                uint32_t r[4];
                ldmx4(r, stb + (uint32_t)(lB + np * 16 * SROW + kk) * 2);
                bf[np*2+0][0] = r[0]; bf[np*2+0][1] = r[1];
                bf[np*2+1][0] = r[2]; bf[np*2+1][1] = r[3];
            }
#pragma unroll
            for (int mi = 0; mi < 4; mi++)
#pragma unroll
                for (int ni = 0; ni < 4; ni++)
                    mma_f16(acc[mi][ni], af[mi], bf[ni]);
        }
    }

    if (MODE == 1) {
#pragma unroll
        for (int mi = 0; mi < 4; mi++)
#pragma unroll
            for (int ni = 0; ni < 4; ni++)
#pragma unroll
                for (int half = 0; half < 2; half++) {
                    int m = m0 + mw + mi * 16 + gr + half * 8;
                    int n = n0 + nw + ni * 8 + 2 * tg;
                    *(float2*)&out[(size_t)m * N + n] =
                        make_float2(acc[mi][ni][half * 2 + 0] + bias[n],
                                    acc[mi][ni][half * 2 + 1] + bias[n + 1]);
                }
    } else if (n0 < 2048) {
#pragma unroll
        for (int mi = 0; mi < 4; mi++)
#pragma unroll
            for (int ni = 0; ni < 4; ni++)
#pragma unroll
                for (int half = 0; half < 2; half++) {
                    int m = m0 + mw + mi * 16 + gr + half * 8;
                    int n = n0 + nw + ni * 8 + 2 * tg;
                    int b = m >> 11, s = m & 2047;
                    int seg = n >> 10, h = (n >> 6) & 15, hd = n & 63;
                    size_t addr = (((size_t)(seg*B_ + b)*H_ + h)*S_ + s)*HD_ + hd;
                    *(__half2*)&g_qkv[addr] =
                        __floats2half2_rn(acc[mi][ni][half*2 + 0] + bias[n],
                                          acc[mi][ni][half*2 + 1] + bias[n + 1]);
                }
    } else {
        // V segment: transpose via smem -> [b][h][hd][s]
        __syncthreads();
        __half* T = smh;   // [128 n][136 m]
#pragma unroll
        for (int mi = 0; mi < 4; mi++)
#pragma unroll
            for (int ni = 0; ni < 4; ni++)
#pragma unroll
                for (int half = 0; half < 2; half++) {
                    int ml = mw + mi * 16 + gr + half * 8;
                    int nl = nw + ni * 8 + 2 * tg;
                    T[(nl + 0) * 136 + ml] = __float2half_rn(acc[mi][ni][half*2 + 0] + bias[n0 + nl]);
                    T[(nl + 1) * 136 + ml] = __float2half_rn(acc[mi][ni][half*2 + 1] + bias[n0 + nl + 1]);
                }
        __syncthreads();
        int b = m0 >> 11, s0 = m0 & 2047;
#pragma unroll
        for (int it = 0; it < 8; it++) {
            int u = it * 256 + tid;
            int nl = u >> 4, blk = u & 15;
            int nn = n0 + nl - 2048;
            int h = nn >> 6, hd = nn & 63;
            uint4 val = *(uint4*)(smw + nl * 68 + blk * 4);
            *(uint4*)&g_qkv[(((size_t)(2*B_ + b)*H_ + h)*HD_ + hd)*S_ + s0 + blk*8] = val;
        }
    }
}

// ---------------------------------------------------------------------------
// fp16 tensorized flash attention (h0 selects head-half). kv-tile 64,
// 3 K/V buffers, ex2.f16x2 softmax, deferred lane reduction.
// grid: (S/128, 32) with bh = (by>>3)*16 + h0 + (by&7).
// ---------------------------------------------------------------------------
#define QS_H 0
#define KS_H 9216
#define VT_H 23040
#define PS_H 36864
#define RS_B 92160
#define ATTN_SMEM (92160 + 2048)   // 94208 B

__global__ __launch_bounds__(256, 2) void attn_tc(int h0)
{
    extern __shared__ __align__(16) __half smh[];
    float* Rs = (float*)((char*)smh + RS_B);
    uint32_t sb = smem_u32(smh);

    int tid  = threadIdx.x;
    int wid  = tid >> 5;
    int lane = tid & 31;
    int gr = lane >> 2, tg = lane & 3;
    int g  = wid >> 2;
    int mq = g * 64;
    int nc = (wid & 3) * 16;

    int bh = ((blockIdx.y >> 3) << 4) + h0 + (blockIdx.y & 7);
    int q0 = blockIdx.x * 128;

    const __half* Qg = g_qkv + ((size_t)(0*64 + bh)*S_ + q0)*HD_;
    const __half* Kg = g_qkv + ((size_t)(1*64 + bh)*S_)*HD_;
    const __half* Vg = g_qkv + ((size_t)(2*64 + bh)*HD_)*S_;   // [hd][s]

    int lQ = (mq + (lane & 15)) * 72 + (lane >> 4) * 8;
    int lKV = (nc + ((lane >> 4) << 3) + (lane & 7)) * 72
            + ((lane >> 3) & 1) * 8;

#pragma unroll
    for (int it = 0; it < 4; it++) {
        int lin = it * 256 + tid;
        int row = lin >> 3, o = (lin & 7) * 8;
        cp16(sb + (uint32_t)(QS_H + row*72 + o)*2, Qg + (size_t)row*HD_ + o);
    }
    cp_commit();

    auto issue_kv = [&](int t) {
        int bsel = t % 3;
#pragma unroll
        for (int it = 0; it < 2; it++) {
            int lin = it * 256 + tid;
            int row = lin >> 3, o = (lin & 7) * 8;
            cp16(sb + (uint32_t)(KS_H + bsel*4608 + row*72 + o)*2,
                 Kg + (size_t)(t*64 + row)*HD_ + o);
            cp16(sb + (uint32_t)(VT_H + bsel*4608 + row*72 + o)*2,
                 Vg + (size_t)row*S_ + t*64 + o);
        }
        cp_commit();
    };

    const int NT = S_/64;
    issue_kv(0);
    issue_kv(1);

    float o_[4][2][4] = {};
    float lrow[8] = {};
    const float CEXP = 0.18033688f;   // log2(e)/8

    for (int t = 0; t < NT; t++) {
        if (t + 1 < NT) cp_wait1(); else cp_wait0();
        __syncthreads();
        if (t + 2 < NT) issue_kv(t + 2);

        uint32_t ksb = sb + (uint32_t)(KS_H + (t % 3) * 4608) * 2;
        uint32_t vsb = sb + (uint32_t)(VT_H + (t % 3) * 4608) * 2;

        float s[4][2][4] = {};
#pragma unroll
        for (int k16 = 0; k16 < 4; k16++) {
            int kk = k16 * 16;
            uint32_t af[4][4], bf[2][2];
#pragma unroll
            for (int mi = 0; mi < 4; mi++)
                ldmx4(af[mi], sb + (uint32_t)(QS_H + lQ + mi * 16 * 72 + kk) * 2);
            {
                uint32_t r[4];
                ldmx4(r, ksb + (uint32_t)(lKV + kk) * 2);
                bf[0][0] = r[0]; bf[0][1] = r[1];
                bf[1][0] = r[2]; bf[1][1] = r[3];
            }
#pragma unroll
            for (int mi = 0; mi < 4; mi++)
#pragma unroll
                for (int ni = 0; ni < 2; ni++)
                    mma_f16(s[mi][ni], af[mi], bf[ni]);
        }

#pragma unroll
        for (int mi = 0; mi < 4; mi++) {
            __half2 hs0 = __float2half2_rn(0.0f);
            __half2 hs1 = __float2half2_rn(0.0f);
#pragma unroll
            for (int ni = 0; ni < 2; ni++) {
                uint32_t y01 = pack_h2(s[mi][ni][0] * CEXP, s[mi][ni][1] * CEXP);
                uint32_t y23 = pack_h2(s[mi][ni][2] * CEXP, s[mi][ni][3] * CEXP);
                uint32_t p01 = ex2_h2(y01);
                uint32_t p23 = ex2_h2(y23);
                int col = nc + ni * 8 + 2 * tg;
                int r0 = mq + mi * 16 + gr;
                *(uint32_t*)&smh[PS_H + (r0 + 0)*72 + col] = p01;
                *(uint32_t*)&smh[PS_H + (r0 + 8)*72 + col] = p23;
                hs0 = __hadd2(hs0, *(__half2*)&p01);
                hs1 = __hadd2(hs1, *(__half2*)&p23);
            }
            float2 f0 = __half22float2(hs0);
            float2 f1 = __half22float2(hs1);
            lrow[mi*2 + 0] += f0.x + f0.y;
            lrow[mi*2 + 1] += f1.x + f1.y;
        }
        bar_named(1 + g, 128);

#pragma unroll
        for (int k16 = 0; k16 < 4; k16++) {
            int kk = k16 * 16;
            uint32_t af[4][4], bf[2][2];
#pragma unroll
            for (int mi = 0; mi < 4; mi++)
                ldmx4(af[mi], sb + (uint32_t)(PS_H + lQ + mi * 16 * 72 + kk) * 2);
            {
                uint32_t r[4];
                ldmx4(r, vsb + (uint32_t)(lKV + kk) * 2);
                bf[0][0] = r[0]; bf[0][1] = r[1];
                bf[1][0] = r[2]; bf[1][1] = r[3];
            }
#pragma unroll
            for (int mi = 0; mi < 4; mi++)
#pragma unroll
                for (int ni = 0; ni < 2; ni++)
                    mma_f16(o_[mi][ni], af[mi], bf[ni]);
        }
    }

#pragma unroll
    for (int i = 0; i < 8; i++) {
        lrow[i] += __shfl_xor_sync(0xffffffffu, lrow[i], 1);
        lrow[i] += __shfl_xor_sync(0xffffffffu, lrow[i], 2);
    }
    if (tg == 0) {
        int slot = wid & 3;
#pragma unroll
        for (int mi = 0; mi < 4; mi++) {
            Rs[slot*128 + mq + mi*16 + gr]     = lrow[mi*2 + 0];
            Rs[slot*128 + mq + mi*16 + gr + 8] = lrow[mi*2 + 1];
        }
    }
    __syncthreads();

    int b = bh >> 4, h = bh & 15;
#pragma unroll
    for (int mi = 0; mi < 4; mi++) {
#pragma unroll
        for (int half = 0; half < 2; half++) {
            int row = mq + mi*16 + gr + half*8;
            float l = Rs[row] + Rs[128 + row] + Rs[256 + row] + Rs[384 + row];
            float inv = 1.0f / l;
#pragma unroll
            for (int ni = 0; ni < 2; ni++) {
                int col = nc + ni*8 + 2*tg;
                size_t base = (size_t)(b*S_ + q0 + row) * D_ + h*HD_ + col;
                *(__half2*)&g_attn[base] =
                    __floats2half2_rn(o_[mi][ni][half*2 + 0] * inv,
                                      o_[mi][ni][half*2 + 1] * inv);
            }
        }
    }
}

// ---------------------------------------------------------------------------
extern "C" void kernel_launch(void* const* d_in, const int* in_sizes, int n_in,
                              void* d_out, int out_size)
{
    const float* x     = (const float*)d_in[0];
    const float* w_in  = (const float*)d_in[1];
    const float* b_in  = (const float*)d_in[2];
    const float* w_out = (const float*)d_in[3];
    const float* b_out = (const float*)d_in[4];
    float* out = (float*)d_out;

    cudaFuncSetAttribute(attn_tc,
                         cudaFuncAttributeMaxDynamicSharedMemorySize, ATTN_SMEM);
    cudaFuncSetAttribute(tc_gemm<0>,
                         cudaFuncAttributeMaxDynamicSharedMemorySize, GE_SMEM);
    cudaFuncSetAttribute(tc_gemm<1>,
                         cudaFuncAttributeMaxDynamicSharedMemorySize, GE_SMEM);

    // fork-join: side stream runs attention for heads 0-7 while the main
    // stream finishes gemm0 for heads 8-15 and runs their attention.
    cudaStream_t s1;
    cudaStreamCreateWithFlags(&s1, cudaStreamNonBlocking);
    cudaEvent_t eA, e1;
    cudaEventCreateWithFlags(&eA, cudaEventDisableTiming);
    cudaEventCreateWithFlags(&e1, cudaEventDisableTiming);

    f2h_all_kernel<<<(N4_ALL + 255)/256, 256>>>((const float4*)x,
                                                (const float4*)w_in,
                                                (const float4*)w_out);

    // gemm0 half A: heads 0-7 (n-tiles {0-3, 8-11, 16-19})
    tc_gemm<0><<<dim3(12, 8192/128), 256, GE_SMEM>>>(b_in, nullptr, 3*D_, D_, 0);
    cudaEventRecord(eA, 0);

    // fork: attention heads 0-7
    cudaStreamWaitEvent(s1, eA, 0);
    attn_tc<<<dim3(S_/128, 32), 256, ATTN_SMEM, s1>>>(0);
    cudaEventRecord(e1, s1);

    // main stream: gemm0 half B (heads 8-15), then their attention
    tc_gemm<0><<<dim3(12, 8192/128), 256, GE_SMEM>>>(b_in, nullptr, 3*D_, D_, 1);
    attn_tc<<<dim3(S_/128, 32), 256, ATTN_SMEM>>>(8);

    // join, then output projection
    cudaStreamWaitEvent(0, e1, 0);
    tc_gemm<1><<<dim3(1024/128, 8192/128), 256, GE_SMEM>>>(b_out, out, D_, D_, 0);
}

// round 16
// speedup vs baseline: 1.0593x; 1.0593x over previous
#include <cuda_runtime.h>
#include <cuda_fp16.h>
#include <cstdint>

#define B_  4
#define S_  2048
#define H_  16
#define HD_ 64
#define D_  1024
#define M_TOT (B_*S_)   // 8192

__device__ __half g_qkv[(size_t)3*B_*H_*S_*HD_]; // seg0 Q [b][h][s][hd], seg1 K same, seg2 V [b][h][hd][s]
__device__ __half g_attn[(size_t)M_TOT*D_];      // [b*s][d]
__device__ __half g_xr[(size_t)M_TOT*D_];
__device__ __half g_w1[(size_t)3*D_*D_];
__device__ __half g_w2[(size_t)D_*D_];

// dependency counters (zeroed by f2h each call)
__device__ int g_cnt_hp[8];
__device__ int g_cnt_m[64];

__device__ __forceinline__ uint32_t smem_u32(const void* p) {
    uint32_t a;
    asm("{ .reg .u64 t; cvta.to.shared.u64 t, %1; cvt.u32.u64 %0, t; }" : "=r"(a) : "l"(p));
    return a;
}
__device__ __forceinline__ void cp16(uint32_t s, const void* g) {
    asm volatile("cp.async.cg.shared.global [%0], [%1], 16;"
                 :: "r"(s), "l"(__cvta_generic_to_global(g)) : "memory");
}
__device__ __forceinline__ void cp_commit() {
    asm volatile("cp.async.commit_group;" ::: "memory");
}
__device__ __forceinline__ void cp_wait0() {
    asm volatile("cp.async.wait_group 0;" ::: "memory");
}
__device__ __forceinline__ void cp_wait1() {
    asm volatile("cp.async.wait_group 1;" ::: "memory");
}
__device__ __forceinline__ void ldmx4(uint32_t* r, uint32_t addr) {
    asm volatile("ldmatrix.sync.aligned.m8n8.x4.shared.b16 {%0,%1,%2,%3}, [%4];"
                 : "=r"(r[0]), "=r"(r[1]), "=r"(r[2]), "=r"(r[3]) : "r"(addr));
}
__device__ __forceinline__ void bar_named(int id, int cnt) {
    asm volatile("bar.sync %0, %1;" :: "r"(id), "r"(cnt) : "memory");
}
__device__ __forceinline__ uint32_t ex2_h2(uint32_t y) {
    uint32_t p;
    asm("ex2.approx.f16x2 %0, %1;" : "=r"(p) : "r"(y));
    return p;
}
__device__ __forceinline__ uint32_t pack_h2(float a, float b) {
    uint32_t r;
    asm("cvt.rn.f16x2.f32 %0, %2, %1;" : "=r"(r) : "f"(a), "f"(b));
    return r;
}

// mma.sync m16n8k16 fp16 in / fp32 accum
__device__ __forceinline__ void mma_f16(float* d, const uint32_t* a, const uint32_t* b) {
    asm volatile(
        "mma.sync.aligned.m16n8k16.row.col.f32.f16.f16.f32 "
        "{%0,%1,%2,%3}, {%4,%5,%6,%7}, {%8,%9}, {%0,%1,%2,%3};"
        : "+f"(d[0]), "+f"(d[1]), "+f"(d[2]), "+f"(d[3])
        : "r"(a[0]), "r"(a[1]), "r"(a[2]), "r"(a[3]), "r"(b[0]), "r"(b[1]));
}

// ---------------------------------------------------------------------------
// Fused fp32 -> fp16 conversion + counter reset (one launch).
// ---------------------------------------------------------------------------
#define N4_X  (M_TOT*D_/4)
#define N4_W1 (3*D_*D_/4)
#define N4_W2 (D_*D_/4)
#define N4_ALL (N4_X + N4_W1 + N4_W2)

__global__ void f2h_all_kernel(const float4* __restrict__ x,
                               const float4* __restrict__ w1,
                               const float4* __restrict__ w2)
{
    if (blockIdx.x == 0 && threadIdx.x < 72) {
        if (threadIdx.x < 8) g_cnt_hp[threadIdx.x] = 0;
        else                 g_cnt_m[threadIdx.x - 8] = 0;
    }
    __half2* dx  = (__half2*)g_xr;
    __half2* dw1 = (__half2*)g_w1;
    __half2* dw2 = (__half2*)g_w2;
    int i = blockIdx.x * blockDim.x + threadIdx.x;
    if (i >= N4_ALL) return;
    const float4* src; __half2* dst; int j;
    if (i < N4_X)              { src = x;  dst = dx;  j = i; }
    else if (i < N4_X + N4_W1) { src = w1; dst = dw1; j = i - N4_X; }
    else                       { src = w2; dst = dw2; j = i - N4_X - N4_W1; }
    float4 v = src[j];
    dst[2*j]   = __floats2half2_rn(v.x, v.y);
    dst[2*j+1] = __floats2half2_rn(v.z, v.w);
}

// ---------------------------------------------------------------------------
// GEMM body (R14-identical): cp.async 3-stage, BK=64, ldmatrix, 128x128 tile.
// ---------------------------------------------------------------------------
#define GBK    64
#define SROW   72
#define STGH   (256*SROW)
#define GE_SMEM (3*STGH*2)            // 110592 B

template<int MODE>
__device__ __forceinline__ void gemm_body(
    const float* __restrict__ bias, float* __restrict__ out,
    int N, int K, int m0, int n0, __half* smh)
{
    uint32_t* smw = (uint32_t*)smh;
    const __half* A = MODE ? g_attn : g_xr;
    const __half* W = MODE ? g_w2   : g_w1;

    int tid  = threadIdx.x;
    int wid  = tid >> 5;
    int lane = tid & 31;
    int gr = lane >> 2, tg = lane & 3;
    int mw = (wid >> 2) * 64;
    int nw = (wid & 3) * 32;
    uint32_t sb = smem_u32(smh);

    int lA = (mw + (lane & 15)) * SROW + (lane >> 4) * 8;
    int lB = (128 + nw + ((lane >> 4) << 3) + (lane & 7)) * SROW
           + ((lane >> 3) & 1) * 8;

    float acc[4][4][4] = {};

    auto issue = [&](int c, int st) {
        int koff = c * GBK;
        uint32_t base = sb + (uint32_t)st * STGH * 2;
#pragma unroll
        for (int it = 0; it < 8; it++) {
            int lin = it * 256 + tid;
            int isB = lin >> 10;
            int row = (lin >> 3) & 127;
            int c8  = (lin & 7) * 8;
            const __half* src = (isB ? W + (size_t)(n0 + row) * K
                                     : A + (size_t)(m0 + row) * K) + koff + c8;
            cp16(base + (uint32_t)isB * (128*SROW*2) + (uint32_t)(row * SROW + c8) * 2, src);
        }
        cp_commit();
    };

    const int NC = K / GBK;
    issue(0, 0);
    if (NC > 1) issue(1, 1);

    for (int c = 0; c < NC; c++) {
        int st = c % 3;
        if (c + 1 < NC) cp_wait1(); else cp_wait0();
        __syncthreads();
        if (c + 2 < NC) issue(c + 2, (c + 2) % 3);

        uint32_t stb = sb + (uint32_t)st * STGH * 2;
#pragma unroll
        for (int k16 = 0; k16 < 4; k16++) {
            int kk = k16 * 16;
            uint32_t af[4][4], bf[4][2];
#pragma unroll
            for (int mi = 0; mi < 4; mi++)
                ldmx4(af[mi], stb + (uint32_t)(lA + mi * 16 * SROW + kk) * 2);
#pragma unroll
            for (int np = 0; np < 2; np++) {
                uint32_t r[4];
                ldmx4(r, stb + (uint32_t)(lB + np * 16 * SROW + kk) * 2);
                bf[np*2+0][0] = r[0]; bf[np*2+0][1] = r[1];
                bf[np*2+1][0] = r[2]; bf[np*2+1][1] = r[3];
            }
#pragma unroll
            for (int mi = 0; mi < 4; mi++)
#pragma unroll
                for (int ni = 0; ni < 4; ni++)
                    mma_f16(acc[mi][ni], af[mi], bf[ni]);
        }
    }

    if (MODE == 1) {
#pragma unroll
        for (int mi = 0; mi < 4; mi++)
#pragma unroll
            for (int ni = 0; ni < 4; ni++)
#pragma unroll
                for (int half = 0; half < 2; half++) {
                    int m = m0 + mw + mi * 16 + gr + half * 8;
                    int n = n0 + nw + ni * 8 + 2 * tg;
                    *(float2*)&out[(size_t)m * N + n] =
                        make_float2(acc[mi][ni][half * 2 + 0] + bias[n],
                                    acc[mi][ni][half * 2 + 1] + bias[n + 1]);
                }
    } else if (n0 < 2048) {
#pragma unroll
        for (int mi = 0; mi < 4; mi++)
#pragma unroll
            for (int ni = 0; ni < 4; ni++)
#pragma unroll
                for (int half = 0; half < 2; half++) {
                    int m = m0 + mw + mi * 16 + gr + half * 8;
                    int n = n0 + nw + ni * 8 + 2 * tg;
                    int b = m >> 11, s = m & 2047;
                    int seg = n >> 10, h = (n >> 6) & 15, hd = n & 63;
                    size_t addr = (((size_t)(seg*B_ + b)*H_ + h)*S_ + s)*HD_ + hd;
                    *(__half2*)&g_qkv[addr] =
                        __floats2half2_rn(acc[mi][ni][half*2 + 0] + bias[n],
                                          acc[mi][ni][half*2 + 1] + bias[n + 1]);
                }
    } else {
        // V segment: transpose via smem -> [b][h][hd][s]
        __syncthreads();
        __half* T = smh;   // [128 n][136 m]
#pragma unroll
        for (int mi = 0; mi < 4; mi++)
#pragma unroll
            for (int ni = 0; ni < 4; ni++)
#pragma unroll
                for (int half = 0; half < 2; half++) {
                    int ml = mw + mi * 16 + gr + half * 8;
                    int nl = nw + ni * 8 + 2 * tg;
                    T[(nl + 0) * 136 + ml] = __float2half_rn(acc[mi][ni][half*2 + 0] + bias[n0 + nl]);
                    T[(nl + 1) * 136 + ml] = __float2half_rn(acc[mi][ni][half*2 + 1] + bias[n0 + nl + 1]);
                }
        __syncthreads();
        int b = m0 >> 11, s0 = m0 & 2047;
#pragma unroll
        for (int it = 0; it < 8; it++) {
            int u = it * 256 + tid;
            int nl = u >> 4, blk = u & 15;
            int nn = n0 + nl - 2048;
            int h = nn >> 6, hd = nn & 63;
            uint4 val = *(uint4*)(smw + nl * 68 + blk * 4);
            *(uint4*)&g_qkv[(((size_t)(2*B_ + b)*H_ + h)*HD_ + hd)*S_ + s0 + blk*8] = val;
        }
    }
}

// ---------------------------------------------------------------------------
// Attention body (R14-identical): kv-tile 64, 3 buffers, ex2.f16x2 softmax.
// ---------------------------------------------------------------------------
#define QS_H 0
#define KS_H 9216
#define VT_H 23040
#define PS_H 36864
#define RS_B 92160

__device__ __forceinline__ void attn_body(int bh, int q0, __half* smh)
{
    float* Rs = (float*)((char*)smh + RS_B);
    uint32_t sb = smem_u32(smh);

    int tid  = threadIdx.x;
    int wid  = tid >> 5;
    int lane = tid & 31;
    int gr = lane >> 2, tg = lane & 3;
    int g  = wid >> 2;
    int mq = g * 64;
    int nc = (wid & 3) * 16;

    const __half* Qg = g_qkv + ((size_t)(0*64 + bh)*S_ + q0)*HD_;
    const __half* Kg = g_qkv + ((size_t)(1*64 + bh)*S_)*HD_;
    const __half* Vg = g_qkv + ((size_t)(2*64 + bh)*HD_)*S_;   // [hd][s]

    int lQ = (mq + (lane & 15)) * 72 + (lane >> 4) * 8;
    int lKV = (nc + ((lane >> 4) << 3) + (lane & 7)) * 72
            + ((lane >> 3) & 1) * 8;

#pragma unroll
    for (int it = 0; it < 4; it++) {
        int lin = it * 256 + tid;
        int row = lin >> 3, o = (lin & 7) * 8;
        cp16(sb + (uint32_t)(QS_H + row*72 + o)*2, Qg + (size_t)row*HD_ + o);
    }
    cp_commit();

    auto issue_kv = [&](int t) {
        int bsel = t % 3;
#pragma unroll
        for (int it = 0; it < 2; it++) {
            int lin = it * 256 + tid;
            int row = lin >> 3, o = (lin & 7) * 8;
            cp16(sb + (uint32_t)(KS_H + bsel*4608 + row*72 + o)*2,
                 Kg + (size_t)(t*64 + row)*HD_ + o);
            cp16(sb + (uint32_t)(VT_H + bsel*4608 + row*72 + o)*2,
                 Vg + (size_t)row*S_ + t*64 + o);
        }
        cp_commit();
    };

    const int NT = S_/64;
    issue_kv(0);
    issue_kv(1);

    float o_[4][2][4] = {};
    float lrow[8] = {};
    const float CEXP = 0.18033688f;   // log2(e)/8

    for (int t = 0; t < NT; t++) {
        if (t + 1 < NT) cp_wait1(); else cp_wait0();
        __syncthreads();
        if (t + 2 < NT) issue_kv(t + 2);

        uint32_t ksb = sb + (uint32_t)(KS_H + (t % 3) * 4608) * 2;
        uint32_t vsb = sb + (uint32_t)(VT_H + (t % 3) * 4608) * 2;

        float s[4][2][4] = {};
#pragma unroll
        for (int k16 = 0; k16 < 4; k16++) {
            int kk = k16 * 16;
            uint32_t af[4][4], bf[2][2];
#pragma unroll
            for (int mi = 0; mi < 4; mi++)
                ldmx4(af[mi], sb + (uint32_t)(QS_H + lQ + mi * 16 * 72 + kk) * 2);
            {
                uint32_t r[4];
                ldmx4(r, ksb + (uint32_t)(lKV + kk) * 2);
                bf[0][0] = r[0]; bf[0][1] = r[1];
                bf[1][0] = r[2]; bf[1][1] = r[3];
            }
#pragma unroll
            for (int mi = 0; mi < 4; mi++)
#pragma unroll
                for (int ni = 0; ni < 2; ni++)
                    mma_f16(s[mi][ni], af[mi], bf[ni]);
        }

#pragma unroll
        for (int mi = 0; mi < 4; mi++) {
            __half2 hs0 = __float2half2_rn(0.0f);
            __half2 hs1 = __float2half2_rn(0.0f);
#pragma unroll
            for (int ni = 0; ni < 2; ni++) {
                uint32_t y01 = pack_h2(s[mi][ni][0] * CEXP, s[mi][ni][1] * CEXP);
                uint32_t y23 = pack_h2(s[mi][ni][2] * CEXP, s[mi][ni][3] * CEXP);
                uint32_t p01 = ex2_h2(y01);
                uint32_t p23 = ex2_h2(y23);
                int col = nc + ni * 8 + 2 * tg;
                int r0 = mq + mi * 16 + gr;
                *(uint32_t*)&smh[PS_H + (r0 + 0)*72 + col] = p01;
                *(uint32_t*)&smh[PS_H + (r0 + 8)*72 + col] = p23;
                hs0 = __hadd2(hs0, *(__half2*)&p01);
                hs1 = __hadd2(hs1, *(__half2*)&p23);
            }
            float2 f0 = __half22float2(hs0);
            float2 f1 = __half22float2(hs1);
            lrow[mi*2 + 0] += f0.x + f0.y;
            lrow[mi*2 + 1] += f1.x + f1.y;
        }
        bar_named(1 + g, 128);

#pragma unroll
        for (int k16 = 0; k16 < 4; k16++) {
            int kk = k16 * 16;
            uint32_t af[4][4], bf[2][2];
#pragma unroll
            for (int mi = 0; mi < 4; mi++)
                ldmx4(af[mi], sb + (uint32_t)(PS_H + lQ + mi * 16 * 72 + kk) * 2);
            {
                uint32_t r[4];
                ldmx4(r, vsb + (uint32_t)(lKV + kk) * 2);
                bf[0][0] = r[0]; bf[0][1] = r[1];
                bf[1][0] = r[2]; bf[1][1] = r[3];
            }
#pragma unroll
            for (int mi = 0; mi < 4; mi++)
#pragma unroll
                for (int ni = 0; ni < 2; ni++)
                    mma_f16(o_[mi][ni], af[mi], bf[ni]);
        }
    }

#pragma unroll
    for (int i = 0; i < 8; i++) {
        lrow[i] += __shfl_xor_sync(0xffffffffu, lrow[i], 1);
        lrow[i] += __shfl_xor_sync(0xffffffffu, lrow[i], 2);
    }
    if (tg == 0) {
        int slot = wid & 3;
#pragma unroll
        for (int mi = 0; mi < 4; mi++) {
            Rs[slot*128 + mq + mi*16 + gr]     = lrow[mi*2 + 0];
            Rs[slot*128 + mq + mi*16 + gr + 8] = lrow[mi*2 + 1];
        }
    }
    __syncthreads();

    int b = bh >> 4, h = bh & 15;
#pragma unroll
    for (int mi = 0; mi < 4; mi++) {
#pragma unroll
        for (int half = 0; half < 2; half++) {
            int row = mq + mi*16 + gr + half*8;
            float l = Rs[row] + Rs[128 + row] + Rs[256 + row] + Rs[384 + row];
            float inv = 1.0f / l;
#pragma unroll
            for (int ni = 0; ni < 2; ni++) {
                int col = nc + ni*8 + 2*tg;
                size_t base = (size_t)(b*S_ + q0 + row) * D_ + h*HD_ + col;
                *(__half2*)&g_attn[base] =
                    __floats2half2_rn(o_[mi][ni][half*2 + 0] * inv,
                                      o_[mi][ni][half*2 + 1] * inv);
            }
        }
    }
}

// ---------------------------------------------------------------------------
// Megakernel: [0,1536) gemm0 (hp-major), [1536,2560) attention (h-major),
// [2560,3072) gemm1 (spins on per-m-tile counters). One launch, no streams.
// ---------------------------------------------------------------------------
__global__ __launch_bounds__(256, 2) void mega_kernel(
    const float* __restrict__ b_in, const float* __restrict__ b_out,
    float* __restrict__ out)
{
    extern __shared__ __align__(16) __half smh[];
    int cid = blockIdx.x;
    if (cid < 1536) {
        int hp = cid / 192, idx = cid - hp * 192;
        int seg = idx >> 6, m = idx & 63;
        gemm_body<0>(b_in, nullptr, 3*D_, D_, m * 128, (seg * 8 + hp) * 128, smh);
        __threadfence();
        __syncthreads();
        if (threadIdx.x == 0) atomicAdd(&g_cnt_hp[hp], 1);
    } else if (cid < 2560) {
        int a = cid - 1536;
        int h = a >> 6, rem = a & 63, b = rem >> 4, qt = rem & 15;
        if (threadIdx.x == 0) {
            while (*(volatile int*)&g_cnt_hp[h >> 1] < 192) __nanosleep(64);
        }
        __syncthreads();
        attn_body(b * 16 + h, qt * 128, smh);
        __threadfence();
        __syncthreads();
        if (threadIdx.x == 0) atomicAdd(&g_cnt_m[b * 16 + qt], 1);
    } else {
        int gidx = cid - 2560;
        int nb = gidx & 7, mb = gidx >> 3;
        if (threadIdx.x == 0) {
            while (*(volatile int*)&g_cnt_m[mb] < 16) __nanosleep(64);
        }
        __syncthreads();
        gemm_body<1>(b_out, out, D_, D_, mb * 128, nb * 128, smh);
    }
}

// ---------------------------------------------------------------------------
extern "C" void kernel_launch(void* const* d_in, const int* in_sizes, int n_in,
                              void* d_out, int out_size)
{
    const float* x     = (const float*)d_in[0];
    const float* w_in  = (const float*)d_in[1];
    const float* b_in  = (const float*)d_in[2];
    const float* w_out = (const float*)d_in[3];
    const float* b_out = (const float*)d_in[4];
    float* out = (float*)d_out;

    cudaFuncSetAttribute(mega_kernel,
                         cudaFuncAttributeMaxDynamicSharedMemorySize, GE_SMEM);

    f2h_all_kernel<<<(N4_ALL + 255)/256, 256>>>((const float4*)x,
                                                (const float4*)w_in,
                                                (const float4*)w_out);

    mega_kernel<<<3072, 256, GE_SMEM>>>(b_in, b_out, out);
}